// round 12
// baseline (speedup 1.0000x reference)
#include <cuda_runtime.h>
#include <cuda_bf16.h>

// NonMaximaSuppression2d: x (8, 64, 256, 256) fp32.
// out[p] = x[p] if x[p] > max(0, 8 replicate-padded neighbors) else 0.
//
// Persistent single-wave grid: 888 blocks (148 SMs x 6 blocks) x 8 warps;
// each warp grid-strides over row-pairs (~9 iterations, data-independent).
// Eliminates ~9 wave transitions + a 78%-empty tail wave of the flat grid.
// Body = champion geometry: 2 rows/warp, 4 independent 256-bit loads
// (ld.global.nc.v8.b32), column-max + 4 shuffles, linear 32-bit addressing.

#define WARPS_PER_BLOCK 8
#define NBLOCKS 888                       // 148 SMs * 6 resident blocks
#define TOTAL_PAIRS (512 * 128)           // 65536
#define STRIDE (NBLOCKS * WARPS_PER_BLOCK) // 7104 warps

__device__ __forceinline__ void load_row8(const float* __restrict__ p8,
                                          float v[8])
{
    unsigned r0, r1, r2, r3, r4, r5, r6, r7;
    asm("ld.global.nc.v8.b32 {%0,%1,%2,%3,%4,%5,%6,%7}, [%8];"
        : "=r"(r0), "=r"(r1), "=r"(r2), "=r"(r3),
          "=r"(r4), "=r"(r5), "=r"(r6), "=r"(r7)
        : "l"(p8));
    v[0] = __uint_as_float(r0); v[1] = __uint_as_float(r1);
    v[2] = __uint_as_float(r2); v[3] = __uint_as_float(r3);
    v[4] = __uint_as_float(r4); v[5] = __uint_as_float(r5);
    v[6] = __uint_as_float(r6); v[7] = __uint_as_float(r7);
}

__device__ __forceinline__ void store_row8(float* __restrict__ p8,
                                           const float o[8])
{
    asm volatile("st.global.v8.b32 [%0], {%1,%2,%3,%4,%5,%6,%7,%8};"
                 :: "l"(p8),
                    "r"(__float_as_uint(o[0])), "r"(__float_as_uint(o[1])),
                    "r"(__float_as_uint(o[2])), "r"(__float_as_uint(o[3])),
                    "r"(__float_as_uint(o[4])), "r"(__float_as_uint(o[5])),
                    "r"(__float_as_uint(o[6])), "r"(__float_as_uint(o[7]))
                 : "memory");
}

// n[j] = max(cm[j-1], cm[j+1]) with replicate clamp at image edges.
__device__ __forceinline__ void hnb(const float cm[8], int lane, float n[8])
{
    float lf = __shfl_up_sync(0xffffffffu, cm[7], 1);
    if (lane == 0) lf = cm[0];                // replicate col 0
    float rt = __shfl_down_sync(0xffffffffu, cm[0], 1);
    if (lane == 31) rt = cm[7];               // replicate col 255

    n[0] = fmaxf(lf,    cm[1]);
#pragma unroll
    for (int j = 1; j < 7; j++)
        n[j] = fmaxf(cm[j-1], cm[j+1]);
    n[7] = fmaxf(cm[6], rt);
}

__device__ __forceinline__ void do_pair(const float* __restrict__ x,
                                        float* __restrict__ out,
                                        int r, int lane)
{
    const int pim  = r & 127;             // pair index within image
    const int lo   = lane * 8;
    const int mid0 = r * 512 + lo;        // row yp   (lane-local)
    const int mid1 = mid0 + 256;          // row yp+1
    const int top  = (pim == 0)   ? mid0 : mid0 - 256;
    const int bot  = (pim == 127) ? mid1 : mid1 + 256;

    // 4 independent 256-bit loads.
    float v0[8], v1[8], v2[8], v3[8];
    load_row8(x + top,  v0);
    load_row8(x + mid0, v1);
    load_row8(x + mid1, v2);
    load_row8(x + bot,  v3);

    float q02[8], q13[8], cma[8], cmb[8];
#pragma unroll
    for (int j = 0; j < 8; j++) {
        q02[j] = fmaxf(v0[j], v2[j]);
        q13[j] = fmaxf(v1[j], v3[j]);
        cma[j] = fmaxf(q02[j], v1[j]);
        cmb[j] = fmaxf(q13[j], v2[j]);
    }

    float na[8], nb[8];
    hnb(cma, lane, na);
    hnb(cmb, lane, nb);

    float oa[8], ob[8];
#pragma unroll
    for (int j = 0; j < 8; j++) {
        float mxa = fmaxf(na[j], fmaxf(q02[j], 0.0f));
        oa[j] = (v1[j] > mxa) ? v1[j] : 0.0f;
        float mxb = fmaxf(nb[j], fmaxf(q13[j], 0.0f));
        ob[j] = (v2[j] > mxb) ? v2[j] : 0.0f;
    }

    store_row8(out + mid0, oa);
    store_row8(out + mid1, ob);
}

__global__ __launch_bounds__(32 * WARPS_PER_BLOCK, 6)
void nms2d_kernel(const float* __restrict__ x, float* __restrict__ out)
{
    const int lane = threadIdx.x & 31;
    const int wgid = blockIdx.x * WARPS_PER_BLOCK + (threadIdx.x >> 5);

    // Grid-stride over row-pairs; iterations are fully independent.
    for (int r = wgid; r < TOTAL_PAIRS; r += STRIDE)
        do_pair(x, out, r, lane);
}

extern "C" void kernel_launch(void* const* d_in, const int* in_sizes, int n_in,
                              void* d_out, int out_size)
{
    const float* x = (const float*)d_in[0];
    float* out = (float*)d_out;

    nms2d_kernel<<<NBLOCKS, 32 * WARPS_PER_BLOCK>>>(x, out);
}

// round 13
// speedup vs baseline: 1.4636x; 1.4636x over previous
#include <cuda_runtime.h>
#include <cuda_bf16.h>

// NonMaximaSuppression2d: x (8, 64, 256, 256) fp32.
// out[p] = x[p] if x[p] > max(0, 8 replicate-padded neighbors) else 0.
//
// Champion geometry, refined: FLAT grid (one warp = one independent
// row-pair; persistent/rolling variants measured 8-45% slower), 4
// independent 256-bit loads + 2 stores per thread (v8.b32, no L2 evict
// hints — hints measured neutral-to-negative), column-max formulation
// with 4 shuffles/warp, fully linear 32-bit addressing.

#define WARPS_PER_BLOCK 8
#define TOTAL_PAIRS (512 * 128)   // 512 images x 128 row-pairs

__device__ __forceinline__ void load_row8(const float* __restrict__ p8,
                                          float v[8])
{
    unsigned r0, r1, r2, r3, r4, r5, r6, r7;
    asm("ld.global.nc.v8.b32 {%0,%1,%2,%3,%4,%5,%6,%7}, [%8];"
        : "=r"(r0), "=r"(r1), "=r"(r2), "=r"(r3),
          "=r"(r4), "=r"(r5), "=r"(r6), "=r"(r7)
        : "l"(p8));
    v[0] = __uint_as_float(r0); v[1] = __uint_as_float(r1);
    v[2] = __uint_as_float(r2); v[3] = __uint_as_float(r3);
    v[4] = __uint_as_float(r4); v[5] = __uint_as_float(r5);
    v[6] = __uint_as_float(r6); v[7] = __uint_as_float(r7);
}

__device__ __forceinline__ void store_row8(float* __restrict__ p8,
                                           const float o[8])
{
    asm volatile("st.global.v8.b32 [%0], {%1,%2,%3,%4,%5,%6,%7,%8};"
                 :: "l"(p8),
                    "r"(__float_as_uint(o[0])), "r"(__float_as_uint(o[1])),
                    "r"(__float_as_uint(o[2])), "r"(__float_as_uint(o[3])),
                    "r"(__float_as_uint(o[4])), "r"(__float_as_uint(o[5])),
                    "r"(__float_as_uint(o[6])), "r"(__float_as_uint(o[7]))
                 : "memory");
}

// n[j] = max(cm[j-1], cm[j+1]) with replicate clamp at image edges.
__device__ __forceinline__ void hnb(const float cm[8], int lane, float n[8])
{
    float lf = __shfl_up_sync(0xffffffffu, cm[7], 1);
    if (lane == 0) lf = cm[0];                // replicate col 0
    float rt = __shfl_down_sync(0xffffffffu, cm[0], 1);
    if (lane == 31) rt = cm[7];               // replicate col 255

    n[0] = fmaxf(lf,    cm[1]);
#pragma unroll
    for (int j = 1; j < 7; j++)
        n[j] = fmaxf(cm[j-1], cm[j+1]);
    n[7] = fmaxf(cm[6], rt);
}

__global__ __launch_bounds__(32 * WARPS_PER_BLOCK, 6)
void nms2d_kernel(const float* __restrict__ x, float* __restrict__ out)
{
    const int warp = threadIdx.x >> 5;
    const int lane = threadIdx.x & 31;
    const int r    = blockIdx.x * WARPS_PER_BLOCK + warp;  // row-pair id
    const int pim  = r & 127;                              // pair index in image

    const int lo   = lane * 8;            // lane element offset within a row
    const int mid0 = r * 512 + lo;        // row yp   (lane-local)
    const int mid1 = mid0 + 256;          // row yp+1

    const int top  = (pim == 0)   ? mid0 : mid0 - 256;   // clamp image top
    const int bot  = (pim == 127) ? mid1 : mid1 + 256;   // clamp image bottom

    // 4 independent 256-bit loads — all issued before any dependent math.
    float v0[8], v1[8], v2[8], v3[8];
    load_row8(x + top,  v0);
    load_row8(x + mid0, v1);
    load_row8(x + mid1, v2);
    load_row8(x + bot,  v3);

    // Column maxes; v0 and v3 die here.
    float q02[8], q13[8], cma[8], cmb[8];
#pragma unroll
    for (int j = 0; j < 8; j++) {
        q02[j] = fmaxf(v0[j], v2[j]);
        q13[j] = fmaxf(v1[j], v3[j]);
        cma[j] = fmaxf(q02[j], v1[j]);
        cmb[j] = fmaxf(q13[j], v2[j]);
    }

    float na[8], nb[8];
    hnb(cma, lane, na);
    hnb(cmb, lane, nb);

    float oa[8], ob[8];
#pragma unroll
    for (int j = 0; j < 8; j++) {
        float mxa = fmaxf(na[j], fmaxf(q02[j], 0.0f));
        oa[j] = (v1[j] > mxa) ? v1[j] : 0.0f;
        float mxb = fmaxf(nb[j], fmaxf(q13[j], 0.0f));
        ob[j] = (v2[j] > mxb) ? v2[j] : 0.0f;
    }

    store_row8(out + mid0, oa);
    store_row8(out + mid1, ob);
}

extern "C" void kernel_launch(void* const* d_in, const int* in_sizes, int n_in,
                              void* d_out, int out_size)
{
    const float* x = (const float*)d_in[0];
    float* out = (float*)d_out;

    const int blocks = TOTAL_PAIRS / WARPS_PER_BLOCK;    // 8192 blocks
    nms2d_kernel<<<blocks, 32 * WARPS_PER_BLOCK>>>(x, out);
}